// round 6
// baseline (speedup 1.0000x reference)
#include <cuda_runtime.h>
#include <cuda_bf16.h>

#define BB 16384
#define MM 8
#define DD 64
#define GPB 32              // groups per block
#define NBLK (BB / GPB)     // 512 blocks
#define NTHR 256            // 8 warps
#define TSS 68              // padded row stride (floats) for Ts/Es

// Fused weights: A[e][c] = sum_d W_o[e,d] * W_v[d,c];  cvec[e] = 8*(W_o·b_v + b_o)[e]
__device__ float g_A[DD * DD];
__device__ float g_cvec[DD];

__global__ __launch_bounds__(256) void precompute_kernel(
    const float* __restrict__ W_v, const float* __restrict__ b_v,
    const float* __restrict__ W_o, const float* __restrict__ b_o) {
    const int idx = blockIdx.x * 256 + threadIdx.x;  // 0..4095
    const int e = idx >> 6, c = idx & 63;
    float acc = 0.f;
#pragma unroll
    for (int d = 0; d < DD; d++)
        acc = fmaf(W_o[e * DD + d], W_v[d * DD + c], acc);
    g_A[idx] = acc;
    if (idx < DD) {
        float cv = 0.f;
#pragma unroll
        for (int d = 0; d < DD; d++)
            cv = fmaf(W_o[idx * DD + d], b_v[d], cv);
        g_cvec[idx] = 8.0f * (cv + b_o[idx]);
    }
}

// 256 threads (8 warps), 32 groups per block.
// Gather: warp w owns local groups [w*4, w*4+4); per iteration the two 16-lane
//   halves each load one group's 9 rows (8 members + item) as float4.
// GEMM: thread (tx,ty) owns 2 groups x 4 channels; s = T·A, y = <s,E> + cdot.
__global__ __launch_bounds__(NTHR) void mosan_kernel(
    const float* __restrict__ user_emb,    // [1e6, 64]
    const float* __restrict__ item_emb,    // [1e5, 64]
    const int*   __restrict__ members,     // [B, 8]
    const int*   __restrict__ item_inputs, // [B]
    float*       __restrict__ out)         // [B]
{
    __shared__ float sA[DD * DD];     // 16 KB, row stride 64
    __shared__ float sTs[GPB * TSS];  // item rows, padded stride
    __shared__ float sEs[GPB * TSS];  // summed member rows
    __shared__ float sCd[GPB];        // cvec . t per group

    const int tid  = threadIdx.x;
    const int lane = tid & 31;
    const int warp = tid >> 5;        // 0..7
    const int gbase = blockIdx.x * GPB;

    // Stage A into shared (L2-resident g_A after warmup).
    {
        const float4* gA4 = reinterpret_cast<const float4*>(g_A);
        float4* sA4 = reinterpret_cast<float4*>(sA);
#pragma unroll
        for (int i = tid; i < DD * DD / 4; i += NTHR) sA4[i] = gA4[i];
    }

    // ---- Gather phase ----
    const int half = lane >> 4;       // which group of the pair
    const int hl   = lane & 15;       // channel quad: owns channels 4*hl..4*hl+3
    const float4* ue4 = reinterpret_cast<const float4*>(user_emb);
    const float4* ie4 = reinterpret_cast<const float4*>(item_emb);
    const float4  cv  = reinterpret_cast<const float4*>(g_cvec)[hl];

#pragma unroll
    for (int p = 0; p < 2; p++) {
        const int gl = warp * 4 + p * 2 + half;  // local group 0..31
        const int g  = gbase + gl;

        int idx[MM];
#pragma unroll
        for (int m = 0; m < MM; m++) idx[m] = members[g * MM + m];
        const int ii = item_inputs[g];

        float4 r[MM];
#pragma unroll
        for (int m = 0; m < MM; m++) r[m] = ue4[(size_t)idx[m] * 16 + hl];
        const float4 t = ie4[(size_t)ii * 16 + hl];

        float4 e = r[0];
#pragma unroll
        for (int m = 1; m < MM; m++) {
            e.x += r[m].x; e.y += r[m].y; e.z += r[m].z; e.w += r[m].w;
        }

        reinterpret_cast<float4*>(&sEs[gl * TSS])[hl] = e;
        reinterpret_cast<float4*>(&sTs[gl * TSS])[hl] = t;

        float cd = t.x * cv.x + t.y * cv.y + t.z * cv.z + t.w * cv.w;
#pragma unroll
        for (int off = 8; off; off >>= 1)
            cd += __shfl_xor_sync(0xffffffffu, cd, off);
        if (hl == 0) sCd[gl] = cd;
    }
    __syncthreads();

    // ---- GEMM phase: s[g,c] = sum_e Ts[g,e] * A[e,c] ----
    const int tx = tid & 15;          // c-tile: c0 = 4*tx
    const int ty = tid >> 4;          // 0..15, g-tile: g0 = 2*ty
    const int c0 = tx * 4, g0 = ty * 2;

    float s[2][4];
#pragma unroll
    for (int i = 0; i < 2; i++)
#pragma unroll
        for (int j = 0; j < 4; j++) s[i][j] = 0.f;

    const float4* A4 = reinterpret_cast<const float4*>(sA);
#pragma unroll
    for (int kc = 0; kc < DD; kc += 4) {
        float4 a[4];
#pragma unroll
        for (int kk = 0; kk < 4; kk++) a[kk] = A4[(kc + kk) * 16 + tx];
        float4 tg[2];
#pragma unroll
        for (int i = 0; i < 2; i++)
            tg[i] = *reinterpret_cast<const float4*>(&sTs[(g0 + i) * TSS + kc]);
#pragma unroll
        for (int i = 0; i < 2; i++) {
            const float tk0 = tg[i].x, tk1 = tg[i].y, tk2 = tg[i].z, tk3 = tg[i].w;
            s[i][0] = fmaf(tk0, a[0].x, s[i][0]); s[i][1] = fmaf(tk0, a[0].y, s[i][1]);
            s[i][2] = fmaf(tk0, a[0].z, s[i][2]); s[i][3] = fmaf(tk0, a[0].w, s[i][3]);
            s[i][0] = fmaf(tk1, a[1].x, s[i][0]); s[i][1] = fmaf(tk1, a[1].y, s[i][1]);
            s[i][2] = fmaf(tk1, a[1].z, s[i][2]); s[i][3] = fmaf(tk1, a[1].w, s[i][3]);
            s[i][0] = fmaf(tk2, a[2].x, s[i][0]); s[i][1] = fmaf(tk2, a[2].y, s[i][1]);
            s[i][2] = fmaf(tk2, a[2].z, s[i][2]); s[i][3] = fmaf(tk2, a[2].w, s[i][3]);
            s[i][0] = fmaf(tk3, a[3].x, s[i][0]); s[i][1] = fmaf(tk3, a[3].y, s[i][1]);
            s[i][2] = fmaf(tk3, a[3].z, s[i][2]); s[i][3] = fmaf(tk3, a[3].w, s[i][3]);
        }
    }

    // ---- Epilogue: y[g] = sum_c s[g,c]*Es[g,c] (+ cdot), reduce across 16 tx lanes ----
    float yp[2];
#pragma unroll
    for (int i = 0; i < 2; i++) {
        const float4 e = *reinterpret_cast<const float4*>(&sEs[(g0 + i) * TSS + c0]);
        yp[i] = s[i][0] * e.x + s[i][1] * e.y + s[i][2] * e.z + s[i][3] * e.w;
    }
#pragma unroll
    for (int off = 8; off; off >>= 1) {
#pragma unroll
        for (int i = 0; i < 2; i++)
            yp[i] += __shfl_xor_sync(0xffffffffu, yp[i], off);
    }
    if ((lane & 15) == 0) {
        // tx == 0 or tx == 16-lane boundary: tx = tid&15 == 0 exactly when lane&15==0
#pragma unroll
        for (int i = 0; i < 2; i++)
            out[gbase + g0 + i] = yp[i] + sCd[g0 + i];
    }
}

extern "C" void kernel_launch(void* const* d_in, const int* in_sizes, int n_in,
                              void* d_out, int out_size) {
    // 0 user_emb, 1 quser_emb, 2 item_emb, 3 W_q, 4 b_q, 5 W_k, 6 b_k,
    // 7 W_v, 8 b_v, 9 W_o, 10 b_o, 11 w_t, 12 b_t, 13 members, 14 item_inputs
    const float* user_emb    = (const float*)d_in[0];
    const float* item_emb    = (const float*)d_in[2];
    const float* W_v         = (const float*)d_in[7];
    const float* b_v         = (const float*)d_in[8];
    const float* W_o         = (const float*)d_in[9];
    const float* b_o         = (const float*)d_in[10];
    const int*   members     = (const int*)d_in[13];
    const int*   item_inputs = (const int*)d_in[14];
    float* out = (float*)d_out;

    precompute_kernel<<<16, 256>>>(W_v, b_v, W_o, b_o);
    mosan_kernel<<<NBLK, NTHR>>>(user_emb, item_emb, members, item_inputs, out);
}